// round 5
// baseline (speedup 1.0000x reference)
#include <cuda_runtime.h>

// PCEN: smooth[t] = 0.975*smooth[t-1] + 0.025*x[t], smooth[0]=x[0]
//       out = (x * (smooth+1e-6)^-0.98 + 2)^0.5 - 2^0.5
//
// Chunked scan with lookback. CHUNK=LOOK=256 (0.975^256 ~ 1.5e-3 decay ->
// ~1.4e-4 output error, empirically 0.09x the decay bound). Single-warp
// blocks (32 rows x 1 chunk): no bar.sync, 2-stage cp.async pipeline,
// coalesced staging into padded SMEM, serial per-row EMA from SMEM,
// in-place transform, cooperative streaming stores (__stcs -> output
// never pollutes L2, preserving L2 for lookback reuse of the previous
// chunk's body).

namespace {

constexpr int T_LEN  = 4096;
constexpr int CHUNK  = 256;
constexpr int LOOK   = 256;
constexpr int CPR    = T_LEN / CHUNK;   // 16
constexpr int RPB    = 32;              // rows per block == threads (1 warp)
constexpr int TILE   = 32;              // floats per tile per row
constexpr int TF4    = TILE / 4;        // 8
constexpr int PAD    = 9;               // smem row stride in float4
constexpr int STAGES = 2;

__device__ __forceinline__ float pcen_pt(float xv, float sm) {
    float l = __log2f(sm + 1e-6f);                // MUFU.LG2
    float g = exp2f(-0.98f * l);                  // MUFU.EX2
    float v = fmaf(xv, g, 2.0f);
    return rsqrtf(v) * v - 1.41421356237309515f;  // MUFU.RSQ; v >= 2
}

__global__ __launch_bounds__(RPB, 24)
void pcen_kernel(const float* __restrict__ x, float* __restrict__ out,
                 int ngroups) {
    __shared__ float4 buf[STAGES][RPB * PAD];

    const int tid      = threadIdx.x;
    const int rowgroup = blockIdx.x % ngroups;
    const int chunk    = blockIdx.x / ngroups;
    const int row0     = rowgroup * RPB;

    const int cs = chunk * CHUNK;
    const int ws = max(0, cs - LOOK);               // window start (mult of 32)
    const int n_tiles  = (cs + CHUNK - ws) / TILE;  // 8 (chunk 0) or 16
    const int out_from = (cs - ws) / TILE;          // 0 or 8

    const float* xbase = x + (size_t)row0 * T_LEN + ws;
    float4* obase = reinterpret_cast<float4*>(out) +
                    (size_t)row0 * (T_LEN / 4) + cs / 4;

    // cooperative copy: lanes 0..7 cover 32 consecutive floats of one row.
    const int cr = tid >> 3;   // 0..3
    const int cf = tid & 7;

    auto issue_tile = [&](int k) {
        if (k < n_tiles) {
            const float* g0 = xbase + k * TILE;
            float4* b = buf[k % STAGES];
            #pragma unroll
            for (int i = 0; i < 8; ++i) {
                int r = cr + i * 4;
                const float* g = g0 + (size_t)r * T_LEN + cf * 4;
                unsigned s = (unsigned)__cvta_generic_to_shared(&b[r * PAD + cf]);
                asm volatile("cp.async.cg.shared.global [%0], [%1], 16;\n"
                             :: "r"(s), "l"(g));
            }
        }
        asm volatile("cp.async.commit_group;\n");
    };

    issue_tile(0);
    issue_tile(1);

    float sm = 0.0f;
    constexpr float S = 0.025f, OMS = 0.975f;

    for (int k = 0; k < n_tiles; ++k) {
        asm volatile("cp.async.wait_group 1;\n");   // tile k is resident
        __syncwarp();

        float4* myrow = &buf[k % STAGES][tid * PAD];
        const bool emit = (k >= out_from);

        #pragma unroll
        for (int f = 0; f < TF4; ++f) {
            float4 v = myrow[f];
            if (k == 0 && f == 0) sm = v.x;          // exact init
            else                  sm = fmaf(OMS, sm, S * v.x);
            float s0 = sm;
            sm = fmaf(OMS, sm, S * v.y);  float s1 = sm;
            sm = fmaf(OMS, sm, S * v.z);  float s2 = sm;
            sm = fmaf(OMS, sm, S * v.w);  float s3 = sm;
            if (emit) {
                float4 o;
                o.x = pcen_pt(v.x, s0);
                o.y = pcen_pt(v.y, s1);
                o.z = pcen_pt(v.z, s2);
                o.w = pcen_pt(v.w, s3);
                myrow[f] = o;                        // in-place
            }
        }
        __syncwarp();

        if (emit) {
            const int ko = k - out_from;
            const float4* b = buf[k % STAGES];
            #pragma unroll
            for (int i = 0; i < 8; ++i) {
                int r = cr + i * 4;
                __stcs(&obase[(size_t)r * (T_LEN / 4) + ko * TF4 + cf],
                       b[r * PAD + cf]);
            }
            __syncwarp();
        }

        issue_tile(k + 2);   // safe: compute/store of tile k done (same slot)
    }
}

}  // namespace

extern "C" void kernel_launch(void* const* d_in, const int* in_sizes, int n_in,
                              void* d_out, int out_size) {
    const float* x = (const float*)d_in[0];
    float* out = (float*)d_out;
    int nrows = in_sizes[0] / T_LEN;        // 8192
    int ngroups = nrows / RPB;              // 256
    int grid = ngroups * CPR;               // 4096 blocks
    pcen_kernel<<<grid, RPB>>>(x, out, ngroups);
}